// round 11
// baseline (speedup 1.0000x reference)
#include <cuda_runtime.h>
#include <cuda_fp16.h>
#include <cstdint>

#define NS     64
#define HID    256
#define STEPZ  (5.0f/63.0f)
#define NSECT  4
#define ROWU32 260                       // uint32 per kp-row (256 + 4 pad)
#define ROWB   (ROWU32*4)                // 1040 bytes
#define SECT_U32  (32*ROWU32)            // 8320 (32 kp-rows = 64 k per section)
#define SECT_BYTES (SECT_U32*4)          // 33280

// ---- shared memory byte offsets ----
#define OFF_W2   0                          // 4 x 33280 = 133120 (whole W2 resident)
#define OFF_AC   (NSECT*SECT_BYTES)         // 133120 : float2 ac[2][256] (4096)
#define OFF_W3   (OFF_AC + 4096)            // 137216 : float4 W3[256]    (4096)
#define OFF_B2   (OFF_W3 + 4096)            // 141312 : float b2[256]     (1024)
#define OFF_RED  (OFF_B2 + 1024)            // 142336 : float red[4][128][4] (8192)
#define OFF_AUX  (OFF_RED + 8192)           // 150528 : alpha/r/g/b [128] (2048)
#define OFF_MBAR (OFF_AUX + 2048)           // 152576 : 4 mbarriers
#define SMEM_TOTAL (OFF_MBAR + 64)          // 152640

// W2 pre-packed: [sect][kp_row 32][np 256(+pad)] f16x2 (k even lo, k odd hi)
__device__ __align__(16) uint32_t W2h_g[NSECT * SECT_U32];

// =================== PTX helpers (base-target only) ===================
__device__ __forceinline__ uint32_t smem_u32(const void* p) {
    uint32_t a;
    asm("{ .reg .u64 t; cvta.to.shared.u64 t, %1; cvt.u32.u64 %0, t; }" : "=r"(a) : "l"(p));
    return a;
}
#define MBAR_INIT(a, c) \
    asm volatile("mbarrier.init.shared.b64 [%0], %1;" :: "r"(a), "r"((uint32_t)(c)) : "memory")
#define MBAR_EXPECT_TX(a, b) \
    asm volatile("mbarrier.arrive.expect_tx.shared.b64 _, [%0], %1;" :: "r"(a), "r"((uint32_t)(b)) : "memory")
#define MBAR_INVAL(a) \
    asm volatile("mbarrier.inval.shared.b64 [%0];" :: "r"(a) : "memory")
#define MBAR_WAIT(a, ph) do {                                                   \
    uint32_t _m = (a); uint32_t _p = (ph); uint32_t _d;                         \
    asm volatile("{\n\t.reg .pred p;\n\t"                                       \
        "mbarrier.try_wait.parity.acquire.cta.shared::cta.b64 p, [%1], %2;\n\t" \
        "selp.b32 %0, 1, 0, p;\n\t}" : "=r"(_d) : "r"(_m), "r"(_p) : "memory"); \
    if (!_d) {                                                                  \
        asm volatile("{\n\t.reg .pred P1;\n\t"                                  \
        "WL_%=:\n\t"                                                            \
        "mbarrier.try_wait.parity.acquire.cta.shared::cta.b64 P1, [%0], %1, 0x989680;\n\t" \
        "@P1 bra.uni WD_%=;\n\t bra.uni WL_%=;\n\t WD_%=:\n\t}"                 \
        :: "r"(_m), "r"(_p) : "memory");                                        \
    } } while (0)

__device__ __forceinline__ void bulk_g2s(uint32_t dst, const void* src, uint32_t bytes, uint32_t mbar) {
    asm volatile("cp.async.bulk.shared::cta.global.mbarrier::complete_tx::bytes [%0], [%1], %2, [%3];"
                 :: "r"(dst), "l"(src), "r"(bytes), "r"(mbar) : "memory");
}
// pack two fp32 -> f16x2 (lo = e, hi = o)
__device__ __forceinline__ uint32_t packh(float e, float o) {
    uint32_t r; asm("cvt.rn.f16x2.f32 %0, %1, %2;" : "=r"(r) : "f"(o), "f"(e)); return r;
}
// relu on packed f16x2 (identical to relu-before-round: rn of negative stays
// negative -> max gives 0; positives unaffected)
__device__ __forceinline__ uint32_t relu2(uint32_t x) {
    uint32_t r;
    asm("max.f16x2 %0, %1, %2;" : "=r"(r) : "r"(x), "r"(0u));
    return r;
}
__device__ __forceinline__ void mma16(float* d, const uint32_t* a, uint32_t b0, uint32_t b1) {
    asm volatile("mma.sync.aligned.m16n8k16.row.col.f32.f16.f16.f32 "
        "{%0,%1,%2,%3}, {%4,%5,%6,%7}, {%8,%9}, {%0,%1,%2,%3};"
        : "+f"(d[0]), "+f"(d[1]), "+f"(d[2]), "+f"(d[3])
        : "r"(a[0]), "r"(a[1]), "r"(a[2]), "r"(a[3]), "r"(b0), "r"(b1));
}

// =================== kernel 1: pack W2 to f16x2, permuted layout ===================
__global__ void arrange_w2_kernel(const float* __restrict__ W2) {
    int idx = blockIdx.x * 256 + threadIdx.x;       // 0..32767
    int kp = idx >> 8, n = idx & 255;               // kp = k/2 (0..127)
    float e = W2[(2*kp)     * HID + n];
    float o = W2[(2*kp + 1) * HID + n];
    int sect = kp >> 5;                             // 32 kp-rows per section
    int sub  = (kp >> 3) & 3;                       // k16-step within section
    int t    = kp & 7;                              // kpair within k16
    int np   = (n & ~63) | ((n & 7) << 3) | ((n >> 3) & 7);
    W2h_g[sect * SECT_U32 + (sub * 8 + t) * ROWU32 + np] = packh(e, o);
}

// =================== kernel 2: fused renderer (2 rays / CTA, 512 thr) ===================
__global__ __launch_bounds__(512, 1)
void nerf_mma_kernel(const float* __restrict__ x_pix,
                     const float* __restrict__ intr,
                     const float* __restrict__ c2w,
                     const float* __restrict__ W1, const float* __restrict__ b1,
                     const float* __restrict__ b2,
                     const float* __restrict__ W3, const float* __restrict__ b3,
                     float* __restrict__ out, int nrays, int R)
{
    extern __shared__ char sm[];
    const uint32_t smb = smem_u32(sm);
    float2* ac_s = (float2*)(sm + OFF_AC);      // [2 rays][256]
    float4* w3_s = (float4*)(sm + OFF_W3);
    float*  b2_s = (float*)(sm + OFF_B2);
    float*  red  = (float*)(sm + OFF_RED);      // [4 warpN][128 p][4 ch]
    float*  alph = (float*)(sm + OFF_AUX);      // [128]
    float*  rr_  = alph + 128; float* gg_ = rr_ + 128; float* bb_ = gg_ + 128;

    const uint32_t mb0 = smb + OFF_MBAR;        // 4 mbarriers, one per section

    const int tid  = threadIdx.x;
    const int lane = tid & 31, warp = tid >> 5;
    const int warpM = warp >> 2, warpN = warp & 3;   // 4(M) x 4(N) warp grid
    const int g = lane >> 2, tig = lane & 3;
    const int rl = warpM >> 1;                       // ray-local of this warp

    // --- init 4 mbarriers and launch all 4 section copies (one-shot) ---
    if (tid == 0) {
        #pragma unroll
        for (int s = 0; s < NSECT; s++) {
            MBAR_INIT(mb0 + s*8, 1);
            MBAR_EXPECT_TX(mb0 + s*8, SECT_BYTES);
            bulk_g2s(smb + OFF_W2 + s*SECT_BYTES, &W2h_g[s*SECT_U32],
                     SECT_BYTES, mb0 + s*8);
        }
    }

    // --- setup: (a,c) tables (one (ray,k) per thread), stage W3/b2 ---
    {
        const int r = tid >> 8;                     // ray-local
        const int k = tid & 255;
        const int ray = blockIdx.x * 2 + r;
        const int b   = ray / R;
        const float* Km = intr + b * 9;
        float a00=Km[0],a01=Km[1],a02=Km[2],a10=Km[3],a11=Km[4],a12=Km[5],a20=Km[6],a21=Km[7],a22=Km[8];
        float i00=a11*a22-a12*a21, i01=a02*a21-a01*a22, i02=a01*a12-a02*a11;
        float i10=a12*a20-a10*a22, i11=a00*a22-a02*a20, i12=a02*a10-a00*a12;
        float i20=a10*a21-a11*a20, i21=a01*a20-a00*a21, i22=a00*a11-a01*a10;
        float idet = 1.0f / (a00*i00 + a01*i10 + a02*i20);
        float px = x_pix[ray*2+0], py = x_pix[ray*2+1];
        float dcx=(i00*px+i01*py+i02)*idet, dcy=(i10*px+i11*py+i12)*idet, dcz=(i20*px+i21*py+i22)*idet;
        const float* M = c2w + b * 16;
        float rdx=M[0]*dcx+M[1]*dcy+M[2]*dcz, rdy=M[4]*dcx+M[5]*dcy+M[6]*dcz, rdz=M[8]*dcx+M[9]*dcy+M[10]*dcz;
        float rox=M[3], roy=M[7], roz=M[11];

        float w0=W1[k], w1=W1[HID+k], w2=W1[2*HID+k];
        ac_s[r*HID + k] = make_float2(rox*w0 + roy*w1 + roz*w2 + b1[k],
                                      rdx*w0 + rdy*w1 + rdz*w2);
        if (tid < 256) { w3_s[tid] = ((const float4*)W3)[tid]; b2_s[tid] = b2[tid]; }
    }
    __syncthreads();

    // --- per-warp row z values: s-rows (warpM&1)*32 + mt*16 + {g, g+8} ---
    float zr[2][2];
    #pragma unroll
    for (int mt = 0; mt < 2; mt++) {
        int s0 = (warpM & 1) * 32 + mt * 16 + g;
        zr[mt][0] = fmaf((float)s0, STEPZ, 1.0f);
        zr[mt][1] = fmaf((float)(s0 + 8), STEPZ, 1.0f);
    }

    float d[2][8][4];
    #pragma unroll
    for (int mt = 0; mt < 2; mt++)
        #pragma unroll
        for (int nt = 0; nt < 8; nt++)
            #pragma unroll
            for (int i = 0; i < 4; i++) d[mt][nt][i] = 0.0f;

    const uint32_t bcol = (uint32_t)(warpN * 64 + g * 8) * 4;   // byte offset in row

    // --- main loop: 4 sections x 4 k16-steps, NO syncthreads, one-shot waits ---
    #pragma unroll
    for (int s = 0; s < NSECT; s++) {
        MBAR_WAIT(mb0 + s*8, 0u);
        const char* sect = sm + OFF_W2 + s*SECT_BYTES;

        #pragma unroll
        for (int sub = 0; sub < 4; sub++) {
            const int kbase = s*64 + sub*16;
            // A fragments: h = relu(a + z*c); fp32 fma -> f16x2 pack -> packed relu
            float4 acA = *(const float4*)&ac_s[rl*HID + kbase + 2*tig];
            float4 acB = *(const float4*)&ac_s[rl*HID + kbase + 2*tig + 8];
            uint32_t aF[2][4];
            #pragma unroll
            for (int mt = 0; mt < 2; mt++) {
                float z0 = zr[mt][0], z1 = zr[mt][1];
                aF[mt][0] = relu2(packh(fmaf(z0, acA.y, acA.x), fmaf(z0, acA.w, acA.z)));
                aF[mt][1] = relu2(packh(fmaf(z1, acA.y, acA.x), fmaf(z1, acA.w, acA.z)));
                aF[mt][2] = relu2(packh(fmaf(z0, acB.y, acB.x), fmaf(z0, acB.w, acB.z)));
                aF[mt][3] = relu2(packh(fmaf(z1, acB.y, acB.x), fmaf(z1, acB.w, acB.z)));
            }

            // B fragments: 4 x LDS.128 (8 n-tiles, k-pairs packed)
            const char* row0 = sect + (sub*8 + tig    ) * ROWB + bcol;
            const char* row1 = sect + (sub*8 + tig + 4) * ROWB + bcol;
            uint4 b0a = *(const uint4*)(row0);
            uint4 b0b = *(const uint4*)(row0 + 16);
            uint4 b1a = *(const uint4*)(row1);
            uint4 b1b = *(const uint4*)(row1 + 16);
            uint32_t b0s[8] = {b0a.x,b0a.y,b0a.z,b0a.w, b0b.x,b0b.y,b0b.z,b0b.w};
            uint32_t b1s[8] = {b1a.x,b1a.y,b1a.z,b1a.w, b1b.x,b1b.y,b1b.z,b1b.w};

            #pragma unroll
            for (int nt = 0; nt < 8; nt++) {
                mma16(d[0][nt], aF[0], b0s[nt], b1s[nt]);
                mma16(d[1][nt], aF[1], b0s[nt], b1s[nt]);
            }
        }
    }

    // --- fused epilogue: bias + relu + layer-3 per lane ---
    float4 acc[2][2];
    #pragma unroll
    for (int mt = 0; mt < 2; mt++)
        #pragma unroll
        for (int i = 0; i < 2; i++) acc[mt][i] = make_float4(0.f, 0.f, 0.f, 0.f);

    #pragma unroll
    for (int mt = 0; mt < 2; mt++) {
        #pragma unroll
        for (int nt = 0; nt < 8; nt++) {
            const int j0 = warpN*64 + nt*8 + 2*tig;
            float b2a = b2_s[j0], b2b = b2_s[j0+1];
            float4 w3a = w3_s[j0], w3b = w3_s[j0+1];
            float h00 = fmaxf(d[mt][nt][0] + b2a, 0.0f);
            float h01 = fmaxf(d[mt][nt][1] + b2b, 0.0f);
            float h10 = fmaxf(d[mt][nt][2] + b2a, 0.0f);
            float h11 = fmaxf(d[mt][nt][3] + b2b, 0.0f);
            float4& aA = acc[mt][0];
            aA.x = fmaf(h00, w3a.x, fmaf(h01, w3b.x, aA.x));
            aA.y = fmaf(h00, w3a.y, fmaf(h01, w3b.y, aA.y));
            aA.z = fmaf(h00, w3a.z, fmaf(h01, w3b.z, aA.z));
            aA.w = fmaf(h00, w3a.w, fmaf(h01, w3b.w, aA.w));
            float4& aB = acc[mt][1];
            aB.x = fmaf(h10, w3a.x, fmaf(h11, w3b.x, aB.x));
            aB.y = fmaf(h10, w3a.y, fmaf(h11, w3b.y, aB.y));
            aB.z = fmaf(h10, w3a.z, fmaf(h11, w3b.z, aB.z));
            aB.w = fmaf(h10, w3a.w, fmaf(h11, w3b.w, aB.w));
        }
    }

    #pragma unroll
    for (int off = 1; off <= 2; off <<= 1) {
        #pragma unroll
        for (int mt = 0; mt < 2; mt++)
            #pragma unroll
            for (int i = 0; i < 2; i++) {
                acc[mt][i].x += __shfl_xor_sync(0xFFFFFFFF, acc[mt][i].x, off);
                acc[mt][i].y += __shfl_xor_sync(0xFFFFFFFF, acc[mt][i].y, off);
                acc[mt][i].z += __shfl_xor_sync(0xFFFFFFFF, acc[mt][i].z, off);
                acc[mt][i].w += __shfl_xor_sync(0xFFFFFFFF, acc[mt][i].w, off);
            }
    }
    if (tig == 0) {
        #pragma unroll
        for (int mt = 0; mt < 2; mt++)
            #pragma unroll
            for (int i = 0; i < 2; i++) {
                int p = warpM*32 + mt*16 + i*8 + g;   // = rl*64 + s
                float* dst = &red[(warpN*128 + p)*4];
                dst[0] = acc[mt][i].x; dst[1] = acc[mt][i].y;
                dst[2] = acc[mt][i].z; dst[3] = acc[mt][i].w;
            }
    }
    __syncthreads();

    // --- per-sample alpha / sigmoid (p = ray_local*64 + s) ---
    if (tid < 128) {
        const int p = tid, ss = tid & 63;
        float o0 = b3[0], o1 = b3[1], o2 = b3[2], o3 = b3[3];
        #pragma unroll
        for (int wn = 0; wn < 4; wn++) {
            const float* q = &red[(wn*128 + p)*4];
            o0 += q[0]; o1 += q[1]; o2 += q[2]; o3 += q[3];
        }
        float dist = (ss < NS-1) ? STEPZ : (1000.0f - 6.0f);
        float sg = fmaxf(o0, 0.0f);
        alph[p] = 1.0f - __expf(-sg * dist);
        rr_[p] = 1.0f / (1.0f + __expf(-o1));
        gg_[p] = 1.0f / (1.0f + __expf(-o2));
        bb_[p] = 1.0f / (1.0f + __expf(-o3));
    }
    __syncthreads();

    // --- parallel transmittance scan: warp w owns ray w; lane l holds s=l, s=l+32 ---
    if (warp < 2) {
        const int base = warp * 64;
        const float a0 = alph[base + lane], a1 = alph[base + lane + 32];
        float P = 1.0f - a0;
        #pragma unroll
        for (int off = 1; off < 32; off <<= 1) {
            float t = __shfl_up_sync(0xFFFFFFFF, P, off);
            if (lane >= off) P *= t;
        }
        float Q = 1.0f - a1;
        #pragma unroll
        for (int off = 1; off < 32; off <<= 1) {
            float t = __shfl_up_sync(0xFFFFFFFF, Q, off);
            if (lane >= off) Q *= t;
        }
        const float tot = __shfl_sync(0xFFFFFFFF, P, 31);
        const float w0 = a0 * P;              // inclusive cumprod (matches ref)
        const float w1 = a1 * (tot * Q);
        const float z0 = fmaf((float)lane, STEPZ, 1.0f);
        const float z1 = fmaf((float)(lane + 32), STEPZ, 1.0f);
        float SR = fmaf(w0, rr_[base + lane], w1 * rr_[base + lane + 32]);
        float SG = fmaf(w0, gg_[base + lane], w1 * gg_[base + lane + 32]);
        float SB = fmaf(w0, bb_[base + lane], w1 * bb_[base + lane + 32]);
        float SD = fmaf(w0, z0, w1 * z1);
        float SA = w0 + w1;
        #pragma unroll
        for (int off = 16; off >= 1; off >>= 1) {
            SR += __shfl_xor_sync(0xFFFFFFFF, SR, off);
            SG += __shfl_xor_sync(0xFFFFFFFF, SG, off);
            SB += __shfl_xor_sync(0xFFFFFFFF, SB, off);
            SD += __shfl_xor_sync(0xFFFFFFFF, SD, off);
            SA += __shfl_xor_sync(0xFFFFFFFF, SA, off);
        }
        if (lane == 0) {
            const int ray = blockIdx.x * 2 + warp;
            float bg = 1.0f - SA;
            out[ray*3 + 0] = SR + bg;
            out[ray*3 + 1] = SG + bg;
            out[ray*3 + 2] = SB + bg;
            out[nrays*3 + ray] = SD;
        }
    }

    if (tid == 0) {
        #pragma unroll
        for (int s = 0; s < NSECT; s++) MBAR_INVAL(mb0 + s*8);
    }
}

extern "C" void kernel_launch(void* const* d_in, const int* in_sizes, int n_in,
                              void* d_out, int out_size)
{
    const float* x_pix = (const float*)d_in[0];
    const float* intr  = (const float*)d_in[1];
    const float* c2w   = (const float*)d_in[2];
    const float* W1    = (const float*)d_in[3];
    const float* b1    = (const float*)d_in[4];
    const float* W2    = (const float*)d_in[5];
    const float* b2    = (const float*)d_in[6];
    const float* W3    = (const float*)d_in[7];
    const float* b3    = (const float*)d_in[8];
    float* out = (float*)d_out;

    int nrays = in_sizes[0] / 2;
    int B     = in_sizes[1] / 9;
    int R     = nrays / B;

    arrange_w2_kernel<<<128, 256>>>(W2);

    cudaFuncSetAttribute(nerf_mma_kernel,
                         cudaFuncAttributeMaxDynamicSharedMemorySize, SMEM_TOTAL);
    nerf_mma_kernel<<<nrays/2, 512, SMEM_TOTAL>>>(
        x_pix, intr, c2w, W1, b1, b2, W3, b3, out, nrays, R);
}

// round 12
// speedup vs baseline: 1.5619x; 1.5619x over previous
#include <cuda_runtime.h>
#include <cuda_fp16.h>
#include <cstdint>

#define NS     64
#define HID    256
#define STEPZ  (5.0f/63.0f)
#define NSECT  4
#define ROWU32 260                       // uint32 per kp-row (256 + 4 pad)
#define ROWB   (ROWU32*4)                // 1040 bytes
#define SECT_U32  (32*ROWU32)            // 8320 (32 kp-rows = 64 k per section)
#define SECT_BYTES (SECT_U32*4)          // 33280

// ---- shared memory byte offsets ----
#define OFF_W2   0                          // 4 x 33280 = 133120 (whole W2 resident)
#define OFF_AC   (NSECT*SECT_BYTES)         // 133120 : float2 ac[2][256] (4096)
#define OFF_W3   (OFF_AC + 4096)            // 137216 : float4 W3[256]    (4096)
#define OFF_B2   (OFF_W3 + 4096)            // 141312 : float b2[256]     (1024)
#define OFF_RED  (OFF_B2 + 1024)            // 142336 : float red[2][128][4] (4096)
#define OFF_AUX  (OFF_RED + 4096)           // 146432 : alpha/r/g/b [128] (2048)
#define OFF_MBAR (OFF_AUX + 2048)           // 148480 : 4 mbarriers
#define SMEM_TOTAL (OFF_MBAR + 64)          // 148544

// W2 pre-packed: [sect][kp_row 32][np 256(+pad)] f16x2 (k even lo, k odd hi)
__device__ __align__(16) uint32_t W2h_g[NSECT * SECT_U32];

// =================== PTX helpers (base-target only) ===================
__device__ __forceinline__ uint32_t smem_u32(const void* p) {
    uint32_t a;
    asm("{ .reg .u64 t; cvta.to.shared.u64 t, %1; cvt.u32.u64 %0, t; }" : "=r"(a) : "l"(p));
    return a;
}
#define MBAR_INIT(a, c) \
    asm volatile("mbarrier.init.shared.b64 [%0], %1;" :: "r"(a), "r"((uint32_t)(c)) : "memory")
#define MBAR_EXPECT_TX(a, b) \
    asm volatile("mbarrier.arrive.expect_tx.shared.b64 _, [%0], %1;" :: "r"(a), "r"((uint32_t)(b)) : "memory")
#define MBAR_INVAL(a) \
    asm volatile("mbarrier.inval.shared.b64 [%0];" :: "r"(a) : "memory")
#define MBAR_WAIT(a, ph) do {                                                   \
    uint32_t _m = (a); uint32_t _p = (ph); uint32_t _d;                         \
    asm volatile("{\n\t.reg .pred p;\n\t"                                       \
        "mbarrier.try_wait.parity.acquire.cta.shared::cta.b64 p, [%1], %2;\n\t" \
        "selp.b32 %0, 1, 0, p;\n\t}" : "=r"(_d) : "r"(_m), "r"(_p) : "memory"); \
    if (!_d) {                                                                  \
        asm volatile("{\n\t.reg .pred P1;\n\t"                                  \
        "WL_%=:\n\t"                                                            \
        "mbarrier.try_wait.parity.acquire.cta.shared::cta.b64 P1, [%0], %1, 0x989680;\n\t" \
        "@P1 bra.uni WD_%=;\n\t bra.uni WL_%=;\n\t WD_%=:\n\t}"                 \
        :: "r"(_m), "r"(_p) : "memory");                                        \
    } } while (0)

__device__ __forceinline__ void bulk_g2s(uint32_t dst, const void* src, uint32_t bytes, uint32_t mbar) {
    asm volatile("cp.async.bulk.shared::cta.global.mbarrier::complete_tx::bytes [%0], [%1], %2, [%3];"
                 :: "r"(dst), "l"(src), "r"(bytes), "r"(mbar) : "memory");
}
// pack two fp32 -> f16x2 (lo = e, hi = o)
__device__ __forceinline__ uint32_t packh(float e, float o) {
    uint32_t r; asm("cvt.rn.f16x2.f32 %0, %1, %2;" : "=r"(r) : "f"(o), "f"(e)); return r;
}
__device__ __forceinline__ void mma16(float* d, const uint32_t* a, uint32_t b0, uint32_t b1) {
    asm volatile("mma.sync.aligned.m16n8k16.row.col.f32.f16.f16.f32 "
        "{%0,%1,%2,%3}, {%4,%5,%6,%7}, {%8,%9}, {%0,%1,%2,%3};"
        : "+f"(d[0]), "+f"(d[1]), "+f"(d[2]), "+f"(d[3])
        : "r"(a[0]), "r"(a[1]), "r"(a[2]), "r"(a[3]), "r"(b0), "r"(b1));
}

// =================== kernel 1: pack W2 to f16x2, permuted layout ===================
__global__ void arrange_w2_kernel(const float* __restrict__ W2) {
    int idx = blockIdx.x * 256 + threadIdx.x;       // 0..32767
    int kp = idx >> 8, n = idx & 255;               // kp = k/2 (0..127)
    float e = W2[(2*kp)     * HID + n];
    float o = W2[(2*kp + 1) * HID + n];
    int sect = kp >> 5;                             // 32 kp-rows per section
    int sub  = (kp >> 3) & 3;                       // k16-step within section
    int t    = kp & 7;                              // kpair within k16
    int np   = (n & ~63) | ((n & 7) << 3) | ((n >> 3) & 7);
    W2h_g[sect * SECT_U32 + (sub * 8 + t) * ROWU32 + np] = packh(e, o);
}

// =================== kernel 2: fused renderer (2 rays / CTA, 256 thr) ===================
__global__ __launch_bounds__(256)
void nerf_mma_kernel(const float* __restrict__ x_pix,
                     const float* __restrict__ intr,
                     const float* __restrict__ c2w,
                     const float* __restrict__ W1, const float* __restrict__ b1,
                     const float* __restrict__ b2,
                     const float* __restrict__ W3, const float* __restrict__ b3,
                     float* __restrict__ out, int nrays, int R)
{
    extern __shared__ char sm[];
    const uint32_t smb = smem_u32(sm);
    float2* ac_s = (float2*)(sm + OFF_AC);      // [2 rays][256]
    float4* w3_s = (float4*)(sm + OFF_W3);
    float*  b2_s = (float*)(sm + OFF_B2);
    float*  red  = (float*)(sm + OFF_RED);      // [2 warpN][128 p][4 ch]
    float*  alph = (float*)(sm + OFF_AUX);      // [128]
    float*  rr_  = alph + 128; float* gg_ = rr_ + 128; float* bb_ = gg_ + 128;

    const uint32_t mb0 = smb + OFF_MBAR;        // 4 mbarriers, one per section

    const int tid  = threadIdx.x;
    const int lane = tid & 31, warp = tid >> 5;
    const int warpM = warp >> 1, warpN = warp & 1;   // 4(M) x 2(N) warp grid
    const int g = lane >> 2, tig = lane & 3;
    const int rl = warpM >> 1;                       // ray-local of this warp

    // --- init 4 mbarriers and launch all 4 section copies (one-shot) ---
    if (tid == 0) {
        #pragma unroll
        for (int s = 0; s < NSECT; s++) {
            MBAR_INIT(mb0 + s*8, 1);
            MBAR_EXPECT_TX(mb0 + s*8, SECT_BYTES);
            bulk_g2s(smb + OFF_W2 + s*SECT_BYTES, &W2h_g[s*SECT_U32],
                     SECT_BYTES, mb0 + s*8);
        }
    }

    // --- setup: (a,c) tables for both rays, stage W3/b2 ---
    #pragma unroll
    for (int r = 0; r < 2; r++) {
        const int ray = blockIdx.x * 2 + r;
        const int b   = ray / R;
        const float* Km = intr + b * 9;
        float a00=Km[0],a01=Km[1],a02=Km[2],a10=Km[3],a11=Km[4],a12=Km[5],a20=Km[6],a21=Km[7],a22=Km[8];
        float i00=a11*a22-a12*a21, i01=a02*a21-a01*a22, i02=a01*a12-a02*a11;
        float i10=a12*a20-a10*a22, i11=a00*a22-a02*a20, i12=a02*a10-a00*a12;
        float i20=a10*a21-a11*a20, i21=a01*a20-a00*a21, i22=a00*a11-a01*a10;
        float idet = 1.0f / (a00*i00 + a01*i10 + a02*i20);
        float px = x_pix[ray*2+0], py = x_pix[ray*2+1];
        float dcx=(i00*px+i01*py+i02)*idet, dcy=(i10*px+i11*py+i12)*idet, dcz=(i20*px+i21*py+i22)*idet;
        const float* M = c2w + b * 16;
        float rdx=M[0]*dcx+M[1]*dcy+M[2]*dcz, rdy=M[4]*dcx+M[5]*dcy+M[6]*dcz, rdz=M[8]*dcx+M[9]*dcy+M[10]*dcz;
        float rox=M[3], roy=M[7], roz=M[11];

        int k = tid;
        float w0=W1[k], w1=W1[HID+k], w2=W1[2*HID+k];
        ac_s[r*HID + k] = make_float2(rox*w0 + roy*w1 + roz*w2 + b1[k],
                                      rdx*w0 + rdy*w1 + rdz*w2);
    }
    w3_s[tid] = ((const float4*)W3)[tid];
    b2_s[tid] = b2[tid];
    __syncthreads();

    // --- per-warp row z values: s-rows (warpM&1)*32 + mt*16 + {g, g+8} ---
    float zr[2][2];
    #pragma unroll
    for (int mt = 0; mt < 2; mt++) {
        int s0 = (warpM & 1) * 32 + mt * 16 + g;
        zr[mt][0] = fmaf((float)s0, STEPZ, 1.0f);
        zr[mt][1] = fmaf((float)(s0 + 8), STEPZ, 1.0f);
    }

    float d[2][16][4];
    #pragma unroll
    for (int mt = 0; mt < 2; mt++)
        #pragma unroll
        for (int nt = 0; nt < 16; nt++)
            #pragma unroll
            for (int i = 0; i < 4; i++) d[mt][nt][i] = 0.0f;

    const uint32_t bcol = (uint32_t)(warpN * 2 * 64 + g * 8) * 4;   // byte offset in row

    // --- main loop: 4 sections x 4 k16-steps, NO syncthreads, one-shot waits ---
    #pragma unroll
    for (int s = 0; s < NSECT; s++) {
        MBAR_WAIT(mb0 + s*8, 0u);
        const char* sect = sm + OFF_W2 + s*SECT_BYTES;

        #pragma unroll
        for (int sub = 0; sub < 4; sub++) {
            const int kbase = s*64 + sub*16;
            // A fragments: h = relu(a + z*c), packed f16x2 over k-pairs
            float4 acA = *(const float4*)&ac_s[rl*HID + kbase + 2*tig];
            float4 acB = *(const float4*)&ac_s[rl*HID + kbase + 2*tig + 8];
            uint32_t aF[2][4];
            #pragma unroll
            for (int mt = 0; mt < 2; mt++) {
                float z0 = zr[mt][0], z1 = zr[mt][1];
                aF[mt][0] = packh(fmaxf(fmaf(z0, acA.y, acA.x), 0.f),
                                  fmaxf(fmaf(z0, acA.w, acA.z), 0.f));
                aF[mt][1] = packh(fmaxf(fmaf(z1, acA.y, acA.x), 0.f),
                                  fmaxf(fmaf(z1, acA.w, acA.z), 0.f));
                aF[mt][2] = packh(fmaxf(fmaf(z0, acB.y, acB.x), 0.f),
                                  fmaxf(fmaf(z0, acB.w, acB.z), 0.f));
                aF[mt][3] = packh(fmaxf(fmaf(z1, acB.y, acB.x), 0.f),
                                  fmaxf(fmaf(z1, acB.w, acB.z), 0.f));
            }

            // B fragments: 8 x LDS.128 (16 n-tiles, k-pairs packed)
            const char* row0 = sect + (sub*8 + tig    ) * ROWB + bcol;
            const char* row1 = sect + (sub*8 + tig + 4) * ROWB + bcol;
            uint4 b0a = *(const uint4*)(row0);
            uint4 b0b = *(const uint4*)(row0 + 16);
            uint4 b0c = *(const uint4*)(row0 + 256);
            uint4 b0d = *(const uint4*)(row0 + 272);
            uint4 b1a = *(const uint4*)(row1);
            uint4 b1b = *(const uint4*)(row1 + 16);
            uint4 b1c = *(const uint4*)(row1 + 256);
            uint4 b1d = *(const uint4*)(row1 + 272);
            uint32_t b0s[16] = {b0a.x,b0a.y,b0a.z,b0a.w, b0b.x,b0b.y,b0b.z,b0b.w,
                                b0c.x,b0c.y,b0c.z,b0c.w, b0d.x,b0d.y,b0d.z,b0d.w};
            uint32_t b1s[16] = {b1a.x,b1a.y,b1a.z,b1a.w, b1b.x,b1b.y,b1b.z,b1b.w,
                                b1c.x,b1c.y,b1c.z,b1c.w, b1d.x,b1d.y,b1d.z,b1d.w};

            #pragma unroll
            for (int nt = 0; nt < 16; nt++) {
                mma16(d[0][nt], aF[0], b0s[nt], b1s[nt]);
                mma16(d[1][nt], aF[1], b0s[nt], b1s[nt]);
            }
        }
    }

    // --- fused epilogue: bias + relu + layer-3 per lane ---
    float4 acc[2][2];
    #pragma unroll
    for (int mt = 0; mt < 2; mt++)
        #pragma unroll
        for (int i = 0; i < 2; i++) acc[mt][i] = make_float4(0.f, 0.f, 0.f, 0.f);

    #pragma unroll
    for (int mt = 0; mt < 2; mt++) {
        #pragma unroll
        for (int nt = 0; nt < 16; nt++) {
            const int j0 = warpN*128 + nt*8 + 2*tig;
            float b2a = b2_s[j0], b2b = b2_s[j0+1];
            float4 w3a = w3_s[j0], w3b = w3_s[j0+1];
            float h00 = fmaxf(d[mt][nt][0] + b2a, 0.0f);
            float h01 = fmaxf(d[mt][nt][1] + b2b, 0.0f);
            float h10 = fmaxf(d[mt][nt][2] + b2a, 0.0f);
            float h11 = fmaxf(d[mt][nt][3] + b2b, 0.0f);
            float4& aA = acc[mt][0];
            aA.x = fmaf(h00, w3a.x, fmaf(h01, w3b.x, aA.x));
            aA.y = fmaf(h00, w3a.y, fmaf(h01, w3b.y, aA.y));
            aA.z = fmaf(h00, w3a.z, fmaf(h01, w3b.z, aA.z));
            aA.w = fmaf(h00, w3a.w, fmaf(h01, w3b.w, aA.w));
            float4& aB = acc[mt][1];
            aB.x = fmaf(h10, w3a.x, fmaf(h11, w3b.x, aB.x));
            aB.y = fmaf(h10, w3a.y, fmaf(h11, w3b.y, aB.y));
            aB.z = fmaf(h10, w3a.z, fmaf(h11, w3b.z, aB.z));
            aB.w = fmaf(h10, w3a.w, fmaf(h11, w3b.w, aB.w));
        }
    }

    #pragma unroll
    for (int off = 1; off <= 2; off <<= 1) {
        #pragma unroll
        for (int mt = 0; mt < 2; mt++)
            #pragma unroll
            for (int i = 0; i < 2; i++) {
                acc[mt][i].x += __shfl_xor_sync(0xFFFFFFFF, acc[mt][i].x, off);
                acc[mt][i].y += __shfl_xor_sync(0xFFFFFFFF, acc[mt][i].y, off);
                acc[mt][i].z += __shfl_xor_sync(0xFFFFFFFF, acc[mt][i].z, off);
                acc[mt][i].w += __shfl_xor_sync(0xFFFFFFFF, acc[mt][i].w, off);
            }
    }
    if (tig == 0) {
        #pragma unroll
        for (int mt = 0; mt < 2; mt++)
            #pragma unroll
            for (int i = 0; i < 2; i++) {
                int p = rl*64 + (warpM & 1)*32 + mt*16 + i*8 + g;
                float* dst = &red[(warpN*128 + p)*4];
                dst[0] = acc[mt][i].x; dst[1] = acc[mt][i].y;
                dst[2] = acc[mt][i].z; dst[3] = acc[mt][i].w;
            }
    }
    __syncthreads();

    // --- per-sample alpha / sigmoid (p = ray_local*64 + s) ---
    if (tid < 128) {
        const int p = tid, ss = tid & 63;
        const float* p0 = &red[p*4];
        const float* p1 = &red[(128 + p)*4];
        float o0 = b3[0] + p0[0] + p1[0];
        float o1 = b3[1] + p0[1] + p1[1];
        float o2 = b3[2] + p0[2] + p1[2];
        float o3 = b3[3] + p0[3] + p1[3];
        float dist = (ss < NS-1) ? STEPZ : (1000.0f - 6.0f);
        float sg = fmaxf(o0, 0.0f);
        alph[p] = 1.0f - __expf(-sg * dist);
        rr_[p] = 1.0f / (1.0f + __expf(-o1));
        gg_[p] = 1.0f / (1.0f + __expf(-o2));
        bb_[p] = 1.0f / (1.0f + __expf(-o3));
    }
    __syncthreads();

    // --- parallel transmittance scan: warp w owns ray w; lane l holds s=l, s=l+32 ---
    if (warp < 2) {
        const int base = warp * 64;
        const float a0 = alph[base + lane], a1 = alph[base + lane + 32];
        float P = 1.0f - a0;
        #pragma unroll
        for (int off = 1; off < 32; off <<= 1) {
            float t = __shfl_up_sync(0xFFFFFFFF, P, off);
            if (lane >= off) P *= t;
        }
        float Q = 1.0f - a1;
        #pragma unroll
        for (int off = 1; off < 32; off <<= 1) {
            float t = __shfl_up_sync(0xFFFFFFFF, Q, off);
            if (lane >= off) Q *= t;
        }
        const float tot = __shfl_sync(0xFFFFFFFF, P, 31);
        const float w0 = a0 * P;              // inclusive cumprod (matches ref)
        const float w1 = a1 * (tot * Q);
        const float z0 = fmaf((float)lane, STEPZ, 1.0f);
        const float z1 = fmaf((float)(lane + 32), STEPZ, 1.0f);
        float SR = fmaf(w0, rr_[base + lane], w1 * rr_[base + lane + 32]);
        float SG = fmaf(w0, gg_[base + lane], w1 * gg_[base + lane + 32]);
        float SB = fmaf(w0, bb_[base + lane], w1 * bb_[base + lane + 32]);
        float SD = fmaf(w0, z0, w1 * z1);
        float SA = w0 + w1;
        #pragma unroll
        for (int off = 16; off >= 1; off >>= 1) {
            SR += __shfl_xor_sync(0xFFFFFFFF, SR, off);
            SG += __shfl_xor_sync(0xFFFFFFFF, SG, off);
            SB += __shfl_xor_sync(0xFFFFFFFF, SB, off);
            SD += __shfl_xor_sync(0xFFFFFFFF, SD, off);
            SA += __shfl_xor_sync(0xFFFFFFFF, SA, off);
        }
        if (lane == 0) {
            const int ray = blockIdx.x * 2 + warp;
            float bg = 1.0f - SA;
            out[ray*3 + 0] = SR + bg;
            out[ray*3 + 1] = SG + bg;
            out[ray*3 + 2] = SB + bg;
            out[nrays*3 + ray] = SD;
        }
    }

    if (tid == 0) {
        #pragma unroll
        for (int s = 0; s < NSECT; s++) MBAR_INVAL(mb0 + s*8);
    }
}

extern "C" void kernel_launch(void* const* d_in, const int* in_sizes, int n_in,
                              void* d_out, int out_size)
{
    const float* x_pix = (const float*)d_in[0];
    const float* intr  = (const float*)d_in[1];
    const float* c2w   = (const float*)d_in[2];
    const float* W1    = (const float*)d_in[3];
    const float* b1    = (const float*)d_in[4];
    const float* W2    = (const float*)d_in[5];
    const float* b2    = (const float*)d_in[6];
    const float* W3    = (const float*)d_in[7];
    const float* b3    = (const float*)d_in[8];
    float* out = (float*)d_out;

    int nrays = in_sizes[0] / 2;
    int B     = in_sizes[1] / 9;
    int R     = nrays / B;

    arrange_w2_kernel<<<128, 256>>>(W2);

    cudaFuncSetAttribute(nerf_mma_kernel,
                         cudaFuncAttributeMaxDynamicSharedMemorySize, SMEM_TOTAL);
    nerf_mma_kernel<<<nrays/2, 256, SMEM_TOTAL>>>(
        x_pix, intr, c2w, W1, b1, b2, W3, b3, out, nrays, R);
}